// round 1
// baseline (speedup 1.0000x reference)
#include <cuda_runtime.h>
#include <cstdint>

// Problem constants (fixed by reference)
#define B_GRAPHS 64
#define NODES_PER_G 1600
#define N_NODES (B_GRAPHS * NODES_PER_G)   // 102400
#define F_DIM 128
#define K_CL 16
#define E_EDGES (N_NODES * 32)             // 3276800

// ---------------- device scratch (no allocations allowed) ----------------
__device__ __align__(16) float g_s[N_NODES * K_CL];     // 6.55 MB
__device__ __align__(16) float g_M[N_NODES * K_CL];     // 6.55 MB
__device__ float g_deg[N_NODES];
__device__ float g_adj[B_GRAPHS * K_CL * K_CL];
__device__ float g_cc[B_GRAPHS * K_CL * K_CL];
__device__ float g_num;
__device__ float g_den;
__device__ float g_ortho;

// ---------------- helpers ----------------
__device__ __forceinline__ void red4(float* p, float a, float b, float c, float d) {
    asm volatile("red.global.add.v4.f32 [%0], {%1,%2,%3,%4};"
                 :: "l"(p), "f"(a), "f"(b), "f"(c), "f"(d) : "memory");
}

__device__ __forceinline__ float selu_f(float v) {
    const float scale = 1.0507009873554805f;
    const float alpha = 1.6732632423543772f;
    return v > 0.f ? scale * v : scale * alpha * (expf(v) - 1.f);
}

// sum over the 16-lane group that xor{1,2,4,8} spans
__device__ __forceinline__ float grp16_sum(float v) {
    v += __shfl_xor_sync(0xffffffffu, v, 1);
    v += __shfl_xor_sync(0xffffffffu, v, 2);
    v += __shfl_xor_sync(0xffffffffu, v, 4);
    v += __shfl_xor_sync(0xffffffffu, v, 8);
    return v;
}
__device__ __forceinline__ float grp16_max(float v) {
    v = fmaxf(v, __shfl_xor_sync(0xffffffffu, v, 1));
    v = fmaxf(v, __shfl_xor_sync(0xffffffffu, v, 2));
    v = fmaxf(v, __shfl_xor_sync(0xffffffffu, v, 4));
    v = fmaxf(v, __shfl_xor_sync(0xffffffffu, v, 8));
    return v;
}

__device__ __forceinline__ float blockSum256(float v, float* sh) {
    int t = threadIdx.x;
    sh[t] = v;
    __syncthreads();
    #pragma unroll
    for (int s = 128; s > 0; s >>= 1) {
        if (t < s) sh[t] += sh[t + s];
        __syncthreads();
    }
    float r = sh[0];
    __syncthreads();
    return r;
}

// ---------------- kernel Z: zero scratch ----------------
__global__ void k_zero() {
    int i = blockIdx.x * blockDim.x + threadIdx.x;   // 1600*256 = 409600
    float4 z = make_float4(0.f, 0.f, 0.f, 0.f);
    if (i < N_NODES * K_CL / 4) ((float4*)g_M)[i] = z;
    if (i < N_NODES) g_deg[i] = 0.f;
    if (i == 0) { g_num = 0.f; g_den = 0.f; g_ortho = 0.f; }
}

// ---------------- kernel A: s = softmax(softmax(x@W + b)) ----------------
// one warp per node; lanes split (k = l&15, j-parity = l>>4)
__global__ void k_s(const float* __restrict__ x, const float* __restrict__ W,
                    const float* __restrict__ bvec) {
    __shared__ float sW[F_DIM * K_CL];   // 8 KB
    __shared__ float xs[8][F_DIM];
    int t = threadIdx.x;
    for (int i = t; i < F_DIM * K_CL; i += 256) sW[i] = W[i];
    __syncthreads();

    int w = t >> 5, l = t & 31;
    int node = blockIdx.x * 8 + w;       // grid = N/8 exactly

    // stage x row (coalesced float4)
    ((float4*)xs[w])[l] = ((const float4*)x)[node * (F_DIM / 4) + l];
    __syncwarp();

    int k = l & 15;
    int par = l >> 4;
    float acc = 0.f;
    #pragma unroll
    for (int i = 0; i < 64; i++) {
        int j = 2 * i + par;
        acc = fmaf(xs[w][j], sW[j * K_CL + k], acc);
    }
    acc += __shfl_xor_sync(0xffffffffu, acc, 16);   // combine parities
    acc += bvec[k];

    // softmax #1
    float m = grp16_max(acc);
    float e = expf(acc - m);
    float s1 = e / grp16_sum(e);
    // softmax #2
    m = grp16_max(s1);
    e = expf(s1 - m);
    float s2 = e / grp16_sum(e);

    if (l < 16) g_s[node * K_CL + l] = s2;
}

// ---------------- kernel C: edge scatter  M[src] += w*s[dst], deg[dst] += w --
__global__ void k_edge(const float* __restrict__ ew, const int* __restrict__ esrc,
                       const int* __restrict__ edst) {
    int e = blockIdx.x * blockDim.x + threadIdx.x;   // grid covers E exactly
    int src = esrc[e];
    int dst = edst[e];
    float w = ew[e];
    const float4* sp = ((const float4*)g_s) + dst * 4;
    float4 a = sp[0], b = sp[1], c = sp[2], d = sp[3];
    float* mp = g_M + src * K_CL;
    red4(mp + 0,  w * a.x, w * a.y, w * a.z, w * a.w);
    red4(mp + 4,  w * b.x, w * b.y, w * b.z, w * b.w);
    red4(mp + 8,  w * c.x, w * c.y, w * c.z, w * c.w);
    red4(mp + 12, w * d.x, w * d.y, w * d.z, w * d.w);
    atomicAdd(&g_deg[dst], w);
}

// ---------------- kernel E1: mincut denominator ----------------
__global__ void k_den() {
    int i = blockIdx.x * blockDim.x + threadIdx.x;   // N exactly
    const float4* sp = ((const float4*)g_s) + i * 4;
    float4 a = sp[0], b = sp[1], c = sp[2], d = sp[3];
    float ss = a.x*a.x + a.y*a.y + a.z*a.z + a.w*a.w
             + b.x*b.x + b.y*b.y + b.z*b.z + b.w*b.w
             + c.x*c.x + c.y*c.y + c.z*c.z + c.w*c.w
             + d.x*d.x + d.y*d.y + d.z*d.z + d.w*d.w;
    float v = g_deg[i] * ss;
    // warp reduce
    #pragma unroll
    for (int d2 = 16; d2 > 0; d2 >>= 1) v += __shfl_xor_sync(0xffffffffu, v, d2);
    if ((threadIdx.x & 31) == 0) atomicAdd(&g_den, v);
}

// ---------------- kernel D: per-graph accumulations ----------------
// out_adj[b] = sum s^T M ; CC[b] = sum s^T s ; out_x[b] = selu(S^T X)
#define CHUNK 16
__global__ void k_graph(const float* __restrict__ x, float* __restrict__ out) {
    __shared__ float s_sh[CHUNK][K_CL];
    __shared__ float M_sh[CHUNK][K_CL];
    int b = blockIdx.x;
    int t = threadIdx.x;
    int f = t & 127;
    int half = t >> 7;                // k-block for out_x: k = half*8 + kk
    int k1 = t >> 4, k2 = t & 15;     // (k1,k2) pair for adj/CC
    int base = b * NODES_PER_G;

    float accx[8] = {0.f,0.f,0.f,0.f,0.f,0.f,0.f,0.f};
    float acc_adj = 0.f, acc_cc = 0.f;

    for (int c = 0; c < NODES_PER_G / CHUNK; c++) {
        __syncthreads();
        if (t < CHUNK * 8) {
            int node = t >> 3, part = t & 7;
            int gi = base + c * CHUNK + node;
            if (part < 4)
                ((float4*)s_sh[node])[part] = ((const float4*)g_s)[gi * 4 + part];
            else
                ((float4*)M_sh[node])[part - 4] = ((const float4*)g_M)[gi * 4 + (part - 4)];
        }
        __syncthreads();
        #pragma unroll
        for (int n = 0; n < CHUNK; n++) {
            int gi = base + c * CHUNK + n;
            float xv = __ldg(x + gi * F_DIM + f);
            const float4* s4 = (const float4*)s_sh[n];
            float4 sa = s4[half * 2], sb = s4[half * 2 + 1];
            accx[0] = fmaf(sa.x, xv, accx[0]);
            accx[1] = fmaf(sa.y, xv, accx[1]);
            accx[2] = fmaf(sa.z, xv, accx[2]);
            accx[3] = fmaf(sa.w, xv, accx[3]);
            accx[4] = fmaf(sb.x, xv, accx[4]);
            accx[5] = fmaf(sb.y, xv, accx[5]);
            accx[6] = fmaf(sb.z, xv, accx[6]);
            accx[7] = fmaf(sb.w, xv, accx[7]);
            float sk1 = s_sh[n][k1];
            acc_adj = fmaf(sk1, M_sh[n][k2], acc_adj);
            acc_cc  = fmaf(sk1, s_sh[n][k2], acc_cc);
        }
    }
    g_adj[b * 256 + t] = acc_adj;
    g_cc [b * 256 + t] = acc_cc;
    #pragma unroll
    for (int kk = 0; kk < 8; kk++) {
        int k = half * 8 + kk;
        out[(b * K_CL + k) * F_DIM + f] = selu_f(accx[kk]);
    }
}

// ---------------- kernel F: per-graph finalize ----------------
__global__ void k_fin(float* __restrict__ out) {
    __shared__ float red[256];
    __shared__ float dpool[K_CL];
    int b = blockIdx.x, t = threadIdx.x;
    int k1 = t >> 4, k2 = t & 15;
    float adj = g_adj[b * 256 + t];
    float cc  = g_cc [b * 256 + t];

    // trace -> mincut numerator
    float tr = blockSum256((k1 == k2) ? adj : 0.f, red);
    if (t == 0) atomicAdd(&g_num, tr);

    // CC Frobenius norm and ortho term
    float nrm2 = blockSum256(cc * cc, red);
    float nrm = sqrtf(nrm2);
    float diff = cc / nrm - ((k1 == k2) ? 0.25f : 0.f);
    float dsum = blockSum256(diff * diff, red);
    if (t == 0) atomicAdd(&g_ortho, sqrtf(dsum));

    // mask diagonal, degree-normalize
    float am = (k1 == k2) ? 0.f : adj;
    float rs = grp16_sum(am);            // row sum over k2 (16-lane group)
    float dp = sqrtf(rs) + 1e-12f;
    if (k2 == 0) dpool[k1] = dp;
    __syncthreads();
    out[B_GRAPHS * K_CL * F_DIM + b * 256 + t] = am / (dp * dpool[k2]);
}

// ---------------- kernel G: scalars ----------------
__global__ void k_scalar(float* __restrict__ out) {
    int off = B_GRAPHS * K_CL * F_DIM + B_GRAPHS * K_CL * K_CL;
    out[off + 0] = -g_num / g_den;
    out[off + 1] = g_ortho * (1.0f / (float)B_GRAPHS);
}

// ---------------- launch ----------------
extern "C" void kernel_launch(void* const* d_in, const int* in_sizes, int n_in,
                              void* d_out, int out_size) {
    const float* x    = (const float*)d_in[0];
    const float* W    = (const float*)d_in[1];
    const float* bv   = (const float*)d_in[2];
    const float* ew   = (const float*)d_in[3];
    const int*   esrc = (const int*)d_in[4];
    const int*   edst = (const int*)d_in[5];
    float* out = (float*)d_out;

    k_zero  <<<1600, 256>>>();
    k_s     <<<N_NODES / 8, 256>>>(x, W, bv);
    k_edge  <<<E_EDGES / 256, 256>>>(ew, esrc, edst);
    k_den   <<<N_NODES / 256, 256>>>();
    k_graph <<<B_GRAPHS, 256>>>(x, out);
    k_fin   <<<B_GRAPHS, 256>>>(out);
    k_scalar<<<1, 1>>>(out);
}

// round 2
// speedup vs baseline: 1.8503x; 1.8503x over previous
#include <cuda_runtime.h>
#include <cstdint>

// Problem constants (fixed by reference)
#define B_GRAPHS 64
#define NODES_PER_G 1600
#define N_NODES (B_GRAPHS * NODES_PER_G)   // 102400
#define F_DIM 128
#define K_CL 16
#define E_EDGES (N_NODES * 32)             // 3276800
#define SPLIT 8                            // CTAs per graph for reductions
#define NPART (NODES_PER_G / SPLIT)        // 200 nodes per CTA
#define CHUNK 8

// ---------------- device scratch (no allocations allowed) ----------------
__device__ __align__(16) float g_s[N_NODES * K_CL];     // 6.55 MB
__device__ __align__(16) float g_M[N_NODES * K_CL];     // 6.55 MB
__device__ float g_deg[N_NODES];
__device__ float g_adj[B_GRAPHS * K_CL * K_CL];
__device__ float g_cc[B_GRAPHS * K_CL * K_CL];
__device__ __align__(16) float g_ox[B_GRAPHS * K_CL * F_DIM];  // 524 KB
__device__ float g_num;
__device__ float g_den;
__device__ float g_ortho;

// ---------------- helpers ----------------
__device__ __forceinline__ void red4(float* p, float a, float b, float c, float d) {
    asm volatile("red.global.add.v4.f32 [%0], {%1,%2,%3,%4};"
                 :: "l"(p), "f"(a), "f"(b), "f"(c), "f"(d) : "memory");
}
__device__ __forceinline__ void red1(float* p, float a) {
    asm volatile("red.global.add.f32 [%0], %1;" :: "l"(p), "f"(a) : "memory");
}

__device__ __forceinline__ float selu_f(float v) {
    const float scale = 1.0507009873554805f;
    const float alpha = 1.6732632423543772f;
    return v > 0.f ? scale * v : scale * alpha * (expf(v) - 1.f);
}

__device__ __forceinline__ float grp16_sum(float v) {
    v += __shfl_xor_sync(0xffffffffu, v, 1);
    v += __shfl_xor_sync(0xffffffffu, v, 2);
    v += __shfl_xor_sync(0xffffffffu, v, 4);
    v += __shfl_xor_sync(0xffffffffu, v, 8);
    return v;
}
__device__ __forceinline__ float grp16_max(float v) {
    v = fmaxf(v, __shfl_xor_sync(0xffffffffu, v, 1));
    v = fmaxf(v, __shfl_xor_sync(0xffffffffu, v, 2));
    v = fmaxf(v, __shfl_xor_sync(0xffffffffu, v, 4));
    v = fmaxf(v, __shfl_xor_sync(0xffffffffu, v, 8));
    return v;
}

__device__ __forceinline__ float blockSum256(float v, float* sh) {
    int t = threadIdx.x;
    sh[t] = v;
    __syncthreads();
    #pragma unroll
    for (int s = 128; s > 0; s >>= 1) {
        if (t < s) sh[t] += sh[t + s];
        __syncthreads();
    }
    float r = sh[0];
    __syncthreads();
    return r;
}

// ---------------- kernel Z: zero scratch ----------------
__global__ void __launch_bounds__(256) k_zero() {
    int i = blockIdx.x * blockDim.x + threadIdx.x;   // 1600*256 = 409600
    float4 z = make_float4(0.f, 0.f, 0.f, 0.f);
    if (i < N_NODES * K_CL / 4) ((float4*)g_M)[i] = z;
    if (i < N_NODES) g_deg[i] = 0.f;
    if (i < B_GRAPHS * K_CL * F_DIM / 4) ((float4*)g_ox)[i] = z;
    if (i < B_GRAPHS * K_CL * K_CL / 4) {
        ((float4*)g_adj)[i] = z;
        ((float4*)g_cc)[i] = z;
    }
    if (i == 0) { g_num = 0.f; g_den = 0.f; g_ortho = 0.f; }
}

// ---------------- kernel A: s = softmax(softmax(x@W + b)) ----------------
__global__ void __launch_bounds__(256) k_s(const float* __restrict__ x,
                                           const float* __restrict__ W,
                                           const float* __restrict__ bvec) {
    __shared__ float sW[F_DIM * K_CL];   // 8 KB
    __shared__ float xs[8][F_DIM];
    int t = threadIdx.x;
    for (int i = t; i < F_DIM * K_CL; i += 256) sW[i] = W[i];
    __syncthreads();

    int w = t >> 5, l = t & 31;
    int node = blockIdx.x * 8 + w;       // grid = N/8 exactly

    ((float4*)xs[w])[l] = ((const float4*)x)[node * (F_DIM / 4) + l];
    __syncwarp();

    int k = l & 15;
    int par = l >> 4;
    float acc = 0.f;
    #pragma unroll
    for (int i = 0; i < 64; i++) {
        int j = 2 * i + par;
        acc = fmaf(xs[w][j], sW[j * K_CL + k], acc);
    }
    acc += __shfl_xor_sync(0xffffffffu, acc, 16);
    acc += bvec[k];

    float m = grp16_max(acc);
    float e = expf(acc - m);
    float s1 = e / grp16_sum(e);
    m = grp16_max(s1);
    e = expf(s1 - m);
    float s2 = e / grp16_sum(e);

    if (l < 16) g_s[node * K_CL + l] = s2;
}

// ---------------- kernel SX: per-graph-part  CC += S^T S,  OX += S^T X ----
__global__ void __launch_bounds__(256) k_sx(const float* __restrict__ x) {
    __shared__ float s_sh[CHUNK][K_CL];
    int b = blockIdx.x >> 3;
    int part = blockIdx.x & 7;
    int base = b * NODES_PER_G + part * NPART;
    int t = threadIdx.x;
    int f = t & 127;
    int half = t >> 7;
    int k1 = t >> 4, k2 = t & 15;

    float accx[8] = {0.f,0.f,0.f,0.f,0.f,0.f,0.f,0.f};
    float acc_cc = 0.f;

    for (int c = 0; c < NPART / CHUNK; c++) {
        __syncthreads();
        if (t < CHUNK * 4) {
            int node = t >> 2, p = t & 3;
            ((float4*)s_sh[node])[p] = ((const float4*)g_s)[(base + c * CHUNK + node) * 4 + p];
        }
        __syncthreads();
        #pragma unroll
        for (int n = 0; n < CHUNK; n++) {
            int gi = base + c * CHUNK + n;
            float xv = __ldg(x + gi * F_DIM + f);
            const float4* s4 = (const float4*)s_sh[n];
            float4 sa = s4[half * 2], sb = s4[half * 2 + 1];
            accx[0] = fmaf(sa.x, xv, accx[0]);
            accx[1] = fmaf(sa.y, xv, accx[1]);
            accx[2] = fmaf(sa.z, xv, accx[2]);
            accx[3] = fmaf(sa.w, xv, accx[3]);
            accx[4] = fmaf(sb.x, xv, accx[4]);
            accx[5] = fmaf(sb.y, xv, accx[5]);
            accx[6] = fmaf(sb.z, xv, accx[6]);
            accx[7] = fmaf(sb.w, xv, accx[7]);
            acc_cc = fmaf(s_sh[n][k1], s_sh[n][k2], acc_cc);
        }
    }
    red1(&g_cc[b * 256 + t], acc_cc);
    #pragma unroll
    for (int kk = 0; kk < 8; kk++) {
        int k = half * 8 + kk;
        red1(&g_ox[(b * K_CL + k) * F_DIM + f], accx[kk]);
    }
}

// ---------------- kernel C: edge scatter, 2 edges per thread ----------------
__global__ void __launch_bounds__(256) k_edge(const float* __restrict__ ew,
                                              const int* __restrict__ esrc,
                                              const int* __restrict__ edst) {
    int i = blockIdx.x * blockDim.x + threadIdx.x;   // grid = E/512
    int2 s2 = ((const int2*)esrc)[i];
    int2 d2 = ((const int2*)edst)[i];
    float2 w2 = ((const float2*)ew)[i];

    // hoist all s-row loads before any reduction (memory clobber barrier)
    const float4* sp0 = ((const float4*)g_s) + d2.x * 4;
    const float4* sp1 = ((const float4*)g_s) + d2.y * 4;
    float4 a0 = sp0[0], b0 = sp0[1], c0 = sp0[2], e0 = sp0[3];
    float4 a1 = sp1[0], b1 = sp1[1], c1 = sp1[2], e1 = sp1[3];

    float* mp0 = g_M + s2.x * K_CL;
    float* mp1 = g_M + s2.y * K_CL;
    float w0 = w2.x, w1 = w2.y;
    red4(mp0 + 0,  w0 * a0.x, w0 * a0.y, w0 * a0.z, w0 * a0.w);
    red4(mp0 + 4,  w0 * b0.x, w0 * b0.y, w0 * b0.z, w0 * b0.w);
    red4(mp0 + 8,  w0 * c0.x, w0 * c0.y, w0 * c0.z, w0 * c0.w);
    red4(mp0 + 12, w0 * e0.x, w0 * e0.y, w0 * e0.z, w0 * e0.w);
    red4(mp1 + 0,  w1 * a1.x, w1 * a1.y, w1 * a1.z, w1 * a1.w);
    red4(mp1 + 4,  w1 * b1.x, w1 * b1.y, w1 * b1.z, w1 * b1.w);
    red4(mp1 + 8,  w1 * c1.x, w1 * c1.y, w1 * c1.z, w1 * c1.w);
    red4(mp1 + 12, w1 * e1.x, w1 * e1.y, w1 * e1.z, w1 * e1.w);
    red1(&g_deg[d2.x], w0);
    red1(&g_deg[d2.y], w1);
}

// ---------------- kernel ADJ: per-graph-part  ADJ += S^T M,  den ----------
__global__ void __launch_bounds__(256) k_adj() {
    __shared__ float s_sh[CHUNK][K_CL];
    __shared__ float M_sh[CHUNK][K_CL];
    __shared__ float dg[CHUNK];
    __shared__ float dred[K_CL];
    int b = blockIdx.x >> 3;
    int part = blockIdx.x & 7;
    int base = b * NODES_PER_G + part * NPART;
    int t = threadIdx.x;
    int k1 = t >> 4, k2 = t & 15;

    float acc_adj = 0.f, acc_den = 0.f;

    for (int c = 0; c < NPART / CHUNK; c++) {
        __syncthreads();
        if (t < CHUNK * 8) {
            int node = t >> 3, p = t & 7;
            int gi = base + c * CHUNK + node;
            if (p < 4)
                ((float4*)s_sh[node])[p] = ((const float4*)g_s)[gi * 4 + p];
            else
                ((float4*)M_sh[node])[p - 4] = ((const float4*)g_M)[gi * 4 + (p - 4)];
        } else if (t >= 64 && t < 64 + CHUNK) {
            dg[t - 64] = g_deg[base + c * CHUNK + (t - 64)];
        }
        __syncthreads();
        #pragma unroll
        for (int n = 0; n < CHUNK; n++) {
            float s1 = s_sh[n][k1];
            acc_adj = fmaf(s1, M_sh[n][k2], acc_adj);
            if (k1 == k2) acc_den = fmaf(dg[n] * s1, s1, acc_den);
        }
    }
    red1(&g_adj[b * 256 + t], acc_adj);
    if (k1 == k2) dred[k1] = acc_den;
    __syncthreads();
    if (t == 0) {
        float v = 0.f;
        #pragma unroll
        for (int k = 0; k < K_CL; k++) v += dred[k];
        red1(&g_den, v);
    }
}

// ---------------- kernel F: per-graph finalize ----------------
__global__ void __launch_bounds__(256) k_fin(float* __restrict__ out) {
    __shared__ float red[256];
    __shared__ float dpool[K_CL];
    int b = blockIdx.x, t = threadIdx.x;
    int k1 = t >> 4, k2 = t & 15;
    float adj = g_adj[b * 256 + t];
    float cc  = g_cc [b * 256 + t];

    float tr = blockSum256((k1 == k2) ? adj : 0.f, red);
    if (t == 0) red1(&g_num, tr);

    float nrm2 = blockSum256(cc * cc, red);
    float nrm = sqrtf(nrm2);
    float diff = cc / nrm - ((k1 == k2) ? 0.25f : 0.f);
    float dsum = blockSum256(diff * diff, red);
    if (t == 0) red1(&g_ortho, sqrtf(dsum));

    float am = (k1 == k2) ? 0.f : adj;
    float rs = grp16_sum(am);
    float dp = sqrtf(rs) + 1e-12f;
    if (k2 == 0) dpool[k1] = dp;
    __syncthreads();
    out[B_GRAPHS * K_CL * F_DIM + b * 256 + t] = am / (dp * dpool[k2]);
}

// ---------------- kernel SELU: out_x = selu(g_ox) ----------------
__global__ void __launch_bounds__(256) k_selu(float* __restrict__ out) {
    int i = blockIdx.x * blockDim.x + threadIdx.x;   // 512*256 = 131072
    out[i] = selu_f(g_ox[i]);
}

// ---------------- kernel G: scalars ----------------
__global__ void k_scalar(float* __restrict__ out) {
    int off = B_GRAPHS * K_CL * F_DIM + B_GRAPHS * K_CL * K_CL;
    out[off + 0] = -g_num / g_den;
    out[off + 1] = g_ortho * (1.0f / (float)B_GRAPHS);
}

// ---------------- launch ----------------
extern "C" void kernel_launch(void* const* d_in, const int* in_sizes, int n_in,
                              void* d_out, int out_size) {
    const float* x    = (const float*)d_in[0];
    const float* W    = (const float*)d_in[1];
    const float* bv   = (const float*)d_in[2];
    const float* ew   = (const float*)d_in[3];
    const int*   esrc = (const int*)d_in[4];
    const int*   edst = (const int*)d_in[5];
    float* out = (float*)d_out;

    k_zero  <<<1600, 256>>>();
    k_s     <<<N_NODES / 8, 256>>>(x, W, bv);
    k_sx    <<<B_GRAPHS * SPLIT, 256>>>(x);
    k_edge  <<<E_EDGES / 512, 256>>>(ew, esrc, edst);   // 4th launch -> ncu target
    k_adj   <<<B_GRAPHS * SPLIT, 256>>>();
    k_fin   <<<B_GRAPHS, 256>>>(out);
    k_selu  <<<512, 256>>>(out);
    k_scalar<<<1, 1>>>(out);
}